// round 2
// baseline (speedup 1.0000x reference)
#include <cuda_runtime.h>
#include <cuda_bf16.h>
#include <cstdint>

// Problem constants
#define OUT_F 4096
#define IN_F  4096
#define MDIM  (8 * 2048)   // B*S = 16384

// 64 MB device scratch for dequantized W (tf32-rounded fp32), [OUT_F][IN_F]
__device__ float g_Wdeq[OUT_F * IN_F];

__device__ __forceinline__ uint32_t f32_to_tf32(float x) {
    uint32_t u;
    asm("cvt.rna.tf32.f32 %0, %1;" : "=r"(u) : "f"(x));
    return u;
}

// ---------------------------------------------------------------------------
// Pass 1: dequantize W_q -> g_Wdeq.
// W_q is [64, 262144] row-major; flat = g*262144 + n with o = n/4096... working
// the algebra: flat = o*4096 + i, i.e. W_q flat IS [OUT_F][IN_F] row-major.
// Param index p = (o&63)*4096 + i.
// ---------------------------------------------------------------------------
__global__ void dequant_kernel(const int* __restrict__ Wq,
                               const float* __restrict__ scale,
                               const float* __restrict__ zero) {
    int vid = blockIdx.x * blockDim.x + threadIdx.x;   // vec4 id
    int f = vid * 4;                                    // element id
    if (f >= OUT_F * IN_F) return;
    int o = f >> 12;
    int i = f & 4095;
    int p = ((o & 63) << 12) | i;

    int4   q = *reinterpret_cast<const int4*>(Wq + f);
    float4 z = *reinterpret_cast<const float4*>(zero + p);
    float4 s = *reinterpret_cast<const float4*>(scale + p);

    float4 w;
    w.x = ((float)q.x - z.x) * s.x;
    w.y = ((float)q.y - z.y) * s.y;
    w.z = ((float)q.z - z.z) * s.z;
    w.w = ((float)q.w - z.w) * s.w;

    // Round to tf32 now (round-to-nearest) so the GEMM B-operand carries no
    // truncation bias and needs no cvt in the inner loop.
    uint4 wo;
    wo.x = f32_to_tf32(w.x);
    wo.y = f32_to_tf32(w.y);
    wo.z = f32_to_tf32(w.z);
    wo.w = f32_to_tf32(w.w);
    *reinterpret_cast<uint4*>(g_Wdeq + f) = wo;
}

// ---------------------------------------------------------------------------
// Pass 2: GEMM  C[m][n] = sum_k A[m][k] * W[n][k] + bias[n]
// Tiles: BM=128, BN=128, BK=16. 256 threads (8 warps), warp tile 32(m) x 64(n),
// mma.sync.m16n8k8.tf32, cp.async 2-stage double buffering.
// ---------------------------------------------------------------------------
#define BM 128
#define BN 128
#define BK 16
#define KPAD 4   // row stride 20 floats -> conflict-free fragment loads

__global__ void __launch_bounds__(256, 2)
gemm_tf32_kernel(const float* __restrict__ A,
                 const float* __restrict__ bias,
                 float* __restrict__ C) {
    __shared__ __align__(16) float As[2][BM][BK + KPAD];
    __shared__ __align__(16) float Bs[2][BN][BK + KPAD];

    const float* Bw = g_Wdeq;

    const int tid  = threadIdx.x;
    const int bm   = blockIdx.y * BM;
    const int bn   = blockIdx.x * BN;
    const int warp = tid >> 5;
    const int lane = tid & 31;
    const int wm   = (warp & 3) * 32;   // warp m-offset within block tile
    const int wn   = (warp >> 2) * 64;  // warp n-offset
    const int grp  = lane >> 2;         // 0..7
    const int tig  = lane & 3;          // 0..3

    float c[2][8][4];
#pragma unroll
    for (int mt = 0; mt < 2; mt++)
#pragma unroll
        for (int nt = 0; nt < 8; nt++)
#pragma unroll
            for (int r = 0; r < 4; r++) c[mt][nt][r] = 0.0f;

    // global->shared load mapping: 256 threads, each does 2 rows x 16B per tile
    const int ldrow = tid >> 2;        // 0..63
    const int ldc4  = (tid & 3) * 4;   // float col offset {0,4,8,12}

    const int NT = IN_F / BK;          // 256 k-tiles

#define LOAD_TILE(st, kt)                                                      \
    do {                                                                       \
        int gk = (kt) * BK + ldc4;                                             \
        _Pragma("unroll")                                                      \
        for (int r = 0; r < 2; r++) {                                          \
            int row = ldrow + r * 64;                                          \
            uint32_t sa = (uint32_t)__cvta_generic_to_shared(                  \
                &As[st][row][ldc4]);                                           \
            const float* ga = A + (size_t)(bm + row) * IN_F + gk;              \
            asm volatile("cp.async.cg.shared.global [%0], [%1], 16;\n"         \
                         :: "r"(sa), "l"(ga));                                 \
            uint32_t sb = (uint32_t)__cvta_generic_to_shared(                  \
                &Bs[st][row][ldc4]);                                           \
            const float* gb = Bw + (size_t)(bn + row) * IN_F + gk;             \
            asm volatile("cp.async.cg.shared.global [%0], [%1], 16;\n"         \
                         :: "r"(sb), "l"(gb));                                 \
        }                                                                      \
        asm volatile("cp.async.commit_group;\n");                              \
    } while (0)

    LOAD_TILE(0, 0);

#pragma unroll 1
    for (int kt = 0; kt < NT; kt++) {
        const int st = kt & 1;
        asm volatile("cp.async.wait_group 0;\n");
        __syncthreads();   // tile kt ready in stage st; everyone done with st^1

        if (kt + 1 < NT) LOAD_TILE(st ^ 1, kt + 1);

#pragma unroll
        for (int kk = 0; kk < BK; kk += 8) {
            uint32_t af[2][4], bf[8][2];
#pragma unroll
            for (int mt = 0; mt < 2; mt++) {
                int row = wm + mt * 16 + grp;
                af[mt][0] = f32_to_tf32(As[st][row][kk + tig]);
                af[mt][1] = f32_to_tf32(As[st][row + 8][kk + tig]);
                af[mt][2] = f32_to_tf32(As[st][row][kk + tig + 4]);
                af[mt][3] = f32_to_tf32(As[st][row + 8][kk + tig + 4]);
            }
#pragma unroll
            for (int nt = 0; nt < 8; nt++) {
                int col = wn + nt * 8 + grp;
                bf[nt][0] = __float_as_uint(Bs[st][col][kk + tig]);      // pre-rounded
                bf[nt][1] = __float_as_uint(Bs[st][col][kk + tig + 4]);
            }
#pragma unroll
            for (int mt = 0; mt < 2; mt++)
#pragma unroll
                for (int nt = 0; nt < 8; nt++) {
                    asm volatile(
                        "mma.sync.aligned.m16n8k8.row.col.f32.tf32.tf32.f32 "
                        "{%0,%1,%2,%3}, {%4,%5,%6,%7}, {%8,%9}, {%0,%1,%2,%3};\n"
                        : "+f"(c[mt][nt][0]), "+f"(c[mt][nt][1]),
                          "+f"(c[mt][nt][2]), "+f"(c[mt][nt][3])
                        : "r"(af[mt][0]), "r"(af[mt][1]),
                          "r"(af[mt][2]), "r"(af[mt][3]),
                          "r"(bf[nt][0]), "r"(bf[nt][1]));
                }
        }
        // next iteration's top __syncthreads protects stage reuse
    }

    // Epilogue: add bias, store float2 pairs (cols 2*tig, 2*tig+1 contiguous)
#pragma unroll
    for (int mt = 0; mt < 2; mt++) {
#pragma unroll
        for (int nt = 0; nt < 8; nt++) {
            int row0 = bm + wm + mt * 16 + grp;
            int col  = bn + wn + nt * 8 + tig * 2;
            float b0 = __ldg(bias + col);
            float b1 = __ldg(bias + col + 1);
            float2 v0 = make_float2(c[mt][nt][0] + b0, c[mt][nt][1] + b1);
            float2 v1 = make_float2(c[mt][nt][2] + b0, c[mt][nt][3] + b1);
            *reinterpret_cast<float2*>(C + (size_t)row0 * OUT_F + col) = v0;
            *reinterpret_cast<float2*>(C + (size_t)(row0 + 8) * OUT_F + col) = v1;
        }
    }
}

// ---------------------------------------------------------------------------
// Launch
// ---------------------------------------------------------------------------
extern "C" void kernel_launch(void* const* d_in, const int* in_sizes, int n_in,
                              void* d_out, int out_size) {
    const float* x     = (const float*)d_in[0];  // [16384, 4096] fp32
    const int*   Wq    = (const int*)d_in[1];    // [64, 262144] int32 (u8 values)
    const float* scale = (const float*)d_in[2];  // [1, 262144]
    const float* zero  = (const float*)d_in[3];  // [1, 262144]
    const float* bias  = (const float*)d_in[4];  // [4096]
    float*       out   = (float*)d_out;          // [16384, 4096] fp32

    // Pass 1: dequant (16M elems / 4-wide / 256 threads)
    dequant_kernel<<<(OUT_F * IN_F) / 4 / 256, 256>>>(Wq, scale, zero);

    // Pass 2: GEMM
    dim3 grid(OUT_F / BN, MDIM / BM);   // (32, 128)
    gemm_tf32_kernel<<<grid, 256>>>(x, bias, out);
}